// round 14
// baseline (speedup 1.0000x reference)
#include <cuda_runtime.h>
#include <math.h>

#define N 512
#define G 64                   // persistent CTAs, all co-resident
#define RPC (N / G)            // 8 rows + 8 cols per CTA
#define BLOCK 256              // 8 warps; warp w owns row/col row0+w
#define STRIDE (N + 4)         // conflict-free smem transpose stride
#define MAX_ITERS 1024
#define CONV_EPS 1e-2f

// Epoch-tagged vector entries: lo32 = float value, hi32 = epoch | (converged << 31).
// 8-byte scalar ld.global.cg ONLY (16B vector spin-loads livelocked in R6/R7).
__device__ unsigned long long g_c64[N];
__device__ unsigned long long g_r64[N];

__device__ __forceinline__ unsigned long long ld64cg(const unsigned long long* p) {
    unsigned long long v;
    asm volatile("ld.global.cg.b64 %0, [%1];" : "=l"(v) : "l"(p) : "memory");
    return v;
}
__device__ __forceinline__ void st64cg(unsigned long long* p, unsigned long long v) {
    asm volatile("st.global.cg.b64 [%0], %1;" :: "l"(p), "l"(v) : "memory");
}
__device__ __forceinline__ unsigned long long pack(float v, unsigned tag) {
    return ((unsigned long long)tag << 32) | (unsigned long long)__float_as_uint(v);
}
__device__ __forceinline__ bool tag_is(unsigned long long v, unsigned e) {
    return (((unsigned)(v >> 32)) & 0x7FFFFFFFu) == e;
}

// Poll two addresses for epoch e. TWO interleaved dependent 8B chains per address:
// each chain is the validated load->check->load pattern; the two chains stagger to
// sample at ~RTT/2 period. Aggregate sector rate ~4.4KB/cyc chip-wide < LTS cap.
__device__ __forceinline__ void poll_pair(const unsigned long long* p0,
                                          const unsigned long long* p1,
                                          unsigned e,
                                          unsigned long long& r0,
                                          unsigned long long& r1) {
    // chain A and chain B per address, issued back-to-back (2 outstanding/address)
    unsigned long long a0 = ld64cg(p0), b0 = ld64cg(p0);
    unsigned long long a1 = ld64cg(p1), b1 = ld64cg(p1);
    bool d0 = false, d1 = false;
    for (;;) {
        if (!d0) {
            if (tag_is(a0, e)) { r0 = a0; d0 = true; }
            else if (tag_is(b0, e)) { r0 = b0; d0 = true; }
        }
        if (!d1) {
            if (tag_is(a1, e)) { r1 = a1; d1 = true; }
            else if (tag_is(b1, e)) { r1 = b1; d1 = true; }
        }
        if (d0 && d1) return;
        // reissue only the chains that failed (dependent pacing per chain)
        if (!d0) { a0 = ld64cg(p0); b0 = ld64cg(p0); }
        if (!d1) { a1 = ld64cg(p1); b1 = ld64cg(p1); }
    }
}

__device__ __forceinline__ float warp_sum(float v) {
    #pragma unroll
    for (int off = 16; off > 0; off >>= 1)
        v += __shfl_xor_sync(0xffffffffu, v, off);
    return v;
}

// Warp dot of one staged matrix row (STRIDE layout) against a 512-float smem vector.
// 4 independent accumulators: short FMA dependency chains.
__device__ __forceinline__ float warp_dot(const float* srow, const float* s_vec, int lane) {
    const float4* sa4 = (const float4*)srow;
    const float4* sv4 = (const float4*)s_vec;
    float s0, s1, s2, s3;
    {
        float4 a = sa4[lane],      v = sv4[lane];
        s0 = fmaf(a.x, v.x, fmaf(a.y, v.y, fmaf(a.z, v.z, a.w * v.w)));
    }
    {
        float4 a = sa4[lane + 32], v = sv4[lane + 32];
        s1 = fmaf(a.x, v.x, fmaf(a.y, v.y, fmaf(a.z, v.z, a.w * v.w)));
    }
    {
        float4 a = sa4[lane + 64], v = sv4[lane + 64];
        s2 = fmaf(a.x, v.x, fmaf(a.y, v.y, fmaf(a.z, v.z, a.w * v.w)));
    }
    {
        float4 a = sa4[lane + 96], v = sv4[lane + 96];
        s3 = fmaf(a.x, v.x, fmaf(a.y, v.y, fmaf(a.z, v.z, a.w * v.w)));
    }
    return warp_sum((s0 + s1) + (s2 + s3));
}

__global__ void __launch_bounds__(BLOCK, 1) sinkhorn_flow10(
    const float* __restrict__ w, float* __restrict__ out)
{
    __shared__ float sA [RPC * STRIDE];   // my 8 rows of |W| (warp w writes/reads row w only)
    __shared__ float sAT[RPC * STRIDE];   // my 8 cols of |W|
    __shared__ float s_r[N];              // staged r@e
    __shared__ float s_c[N];              // staged c@(e+1)

    const int tid  = threadIdx.x;
    const int warp = tid >> 5;
    const int lane = tid & 31;
    const int row0 = blockIdx.x * RPC;
    const int my_i = row0 + warp;

    // ---- warp-per-row load: 4 x LDG.128 per lane covering the WHOLE row, then
    //      in-register rowsum -> publish r@1 BEFORE any smem/barrier (critical path).
    float r_mine;
    {
        const float4* wrow = (const float4*)(w + my_i * N);
        float4 a0 = wrow[lane], a1 = wrow[lane + 32], a2 = wrow[lane + 64], a3 = wrow[lane + 96];
        a0 = make_float4(fabsf(a0.x), fabsf(a0.y), fabsf(a0.z), fabsf(a0.w));
        a1 = make_float4(fabsf(a1.x), fabsf(a1.y), fabsf(a1.z), fabsf(a1.w));
        a2 = make_float4(fabsf(a2.x), fabsf(a2.y), fabsf(a2.z), fabsf(a2.w));
        a3 = make_float4(fabsf(a3.x), fabsf(a3.y), fabsf(a3.z), fabsf(a3.w));
        float s = (((a0.x + a0.y) + (a0.z + a0.w)) + ((a1.x + a1.y) + (a1.z + a1.w)))
                + (((a2.x + a2.y) + (a2.z + a2.w)) + ((a3.x + a3.y) + (a3.z + a3.w)));
        r_mine = 1.0f / warp_sum(s);
        if (lane == 0) st64cg(&g_r64[my_i], pack(r_mine, 1u));   // r@1 = 1/rowsum (c@1==1)
        float4* sa4 = (float4*)(sA + warp * STRIDE);
        sa4[lane] = a0; sa4[lane + 32] = a1; sa4[lane + 64] = a2; sa4[lane + 96] = a3;
    }

    // ---- stage my 8 cols while other CTAs publish r@1 (overlap). ----
    {
        const int half = lane & 1;         // which float4 of the 8-col slab
        #pragma unroll
        for (int p = 0; p < 4; ++p) {
            int rr = warp * 64 + p * 16 + (lane >> 1);
            float4 v = *(const float4*)(w + rr * N + row0 + 4 * half);
            sAT[(4 * half + 0) * STRIDE + rr] = fabsf(v.x);
            sAT[(4 * half + 1) * STRIDE + rr] = fabsf(v.y);
            sAT[(4 * half + 2) * STRIDE + rr] = fabsf(v.z);
            sAT[(4 * half + 3) * STRIDE + rr] = fabsf(v.w);
        }
    }
    // sAT is covered by the first in-loop __syncthreads before any warp_dot on it.

    float c_prev = 1.0f;
    unsigned e = 1;
    for (;;) {
        // ---- poll r@e into s_r ----
        {
            unsigned long long v0, v1;
            poll_pair(&g_r64[tid], &g_r64[tid + 256], e, v0, v1);
            s_r[tid]       = __uint_as_float((unsigned)v0);
            s_r[tid + 256] = __uint_as_float((unsigned)v1);
        }
        __syncthreads();                                  // barrier 1 of 2

        // ---- col phase: c@(e+1) = 1/(A^T r@e), publish with conv bit ----
        {
            float c_new = 1.0f / warp_dot(sAT + warp * STRIDE, s_r, lane);
            if (lane == 0) {
                unsigned conv = (fabsf(c_new - c_prev) <= CONV_EPS * fabsf(c_new)) ? 1u : 0u;
                st64cg(&g_c64[my_i], pack(c_new, (e + 1u) | (conv << 31)));
            }
            c_prev = c_new;
        }

        // ---- poll c@(e+1) into s_c; keep words for conv bits ----
        unsigned long long v0, v1;
        poll_pair(&g_c64[tid], &g_c64[tid + 256], e + 1u, v0, v1);
        s_c[tid]       = __uint_as_float((unsigned)v0);
        s_c[tid + 256] = __uint_as_float((unsigned)v1);
        // barrier 2 of 2: the vote IS a full barrier, and all s_c stores precede it,
        // so s_c is safe to read after. Break decision is identical data in every CTA.
        int all_conv = __syncthreads_and((int)((v0 & v1) >> 63));

        // ---- row phase (speculative): r@(e+1) = 1/(A c@(e+1)), publish.
        //      Keeps the break decision off the producer->consumer critical path. ----
        {
            r_mine = 1.0f / warp_dot(sA + warp * STRIDE, s_c, lane);
            if (lane == 0) st64cg(&g_r64[my_i], pack(r_mine, e + 1u));
        }

        if ((e >= 2u && all_conv) || e >= (unsigned)MAX_ITERS) break;
        ++e;
    }

    // ---- finalize: out[i][j] = |W|[i][j] * r@(e+1)_i * c@(e+1)_j ----
    // r_mine is the speculative r@(e+1): rows sum to exactly 1, cols within eps —
    // one extra row-normalization past the break, closer to the fixed point.
    {
        const float4* sa4 = (const float4*)(sA + warp * STRIDE);
        const float4* sv4 = (const float4*)s_c;
        float4* o4 = (float4*)(out + my_i * N);
        #pragma unroll
        for (int u = 0; u < 4; ++u) {
            float4 a = sa4[lane + 32 * u];
            float4 v = sv4[lane + 32 * u];
            o4[lane + 32 * u] = make_float4(a.x * r_mine * v.x,
                                            a.y * r_mine * v.y,
                                            a.z * r_mine * v.z,
                                            a.w * r_mine * v.w);
        }
    }
}

extern "C" void kernel_launch(void* const* d_in, const int* in_sizes, int n_in,
                              void* d_out, int out_size) {
    const float* w = (const float*)d_in[0];
    float* out = (float*)d_out;
    sinkhorn_flow10<<<G, BLOCK>>>(w, out);
}